// round 4
// baseline (speedup 1.0000x reference)
#include <cuda_runtime.h>
#include <cuda_bf16.h>
#include <math.h>
#include <stdint.h>

// Problem constants
#define BB   64      // batch
#define SS   64      // encoder seq len
#define TT   32      // decoder target len
#define VV   32000   // vocab
#define EE   256     // embedding
#define HH   512     // hidden
#define H3   1536    // 3*H

#define GRU_CTAS 128 // persistent GRU grid (single wave on 148 SMs)

// -------------------- device scratch (static, no allocation) --------------------
__device__ __align__(16) float          g_h[2][BB * HH];     // double-buffered hidden
__device__ __align__(16) float          g_gpart[6][BB * H3]; // split-K partials, gates
__device__ __align__(16) float          g_hpart[8][BB * HH]; // split-K partials, candidate
__device__ __align__(16) __nv_bfloat16  g_hb[BB * HH];       // hidden in bf16 (fc A operand)
__device__ __align__(16) __nv_bfloat16  g_wt[(size_t)VV * HH]; // fc_W transposed [v][k] bf16
__device__ __align__(16) float          g_logits[(size_t)BB * VV];
__device__ float                        g_ce[BB];
__device__ int                          g_tok[BB];
__device__ unsigned                     g_bar;               // grid barrier counter

__device__ __forceinline__ float sigf(float x) { return 1.0f / (1.0f + expf(-x)); }

// Software grid barrier (counting). All GRU_CTAS CTAs must call with the same target.
__device__ __forceinline__ void grid_bar(unsigned target) {
    __syncthreads();
    if (threadIdx.x == 0) {
        __threadfence();                       // release: publish phase writes
        atomicAdd(&g_bar, 1u);
        volatile unsigned* vp = &g_bar;
        while (*vp < target) __nanosleep(64);
    }
    __syncthreads();
    __threadfence();                           // acquire side
}

// -------------------- init --------------------
__global__ void k_init(float* out) {
    int b = blockIdx.x, t = threadIdx.x;
    g_h[0][b * HH + t] = 0.0f;
    if (t == 0) g_tok[b] = 1;                  // BEGIN token
    if (b == 0 && t == 0) { out[0] = 0.0f; g_bar = 0u; }
}

// -------------------- fc_W [k][v] fp32 -> g_wt [v][k] bf16 (transpose) --------------------
// grid = (1000, 16), 256 threads; 32x32 tiles.
__global__ void k_prept(const float* __restrict__ fcW) {
    __shared__ float Ts[32][33];
    int v0 = blockIdx.x * 32, k0 = blockIdx.y * 32;
    int c = threadIdx.x & 31, r8 = threadIdx.x >> 5;   // 8 rows per pass
    #pragma unroll
    for (int i = 0; i < 4; i++) {
        int r = r8 + 8 * i;
        Ts[r][c] = fcW[(size_t)(k0 + r) * VV + v0 + c];
    }
    __syncthreads();
    #pragma unroll
    for (int i = 0; i < 4; i++) {
        int r = r8 + 8 * i;
        g_wt[(size_t)(v0 + r) * HH + k0 + c] = __float2bfloat16(Ts[c][r]);
    }
}

// -------------------- fused GRU sequence kernel --------------------
// One launch = nsteps GRU steps. 3 phases per step separated by grid barriers.
// Phase A: gate GEMM split-K partials (112 working CTAs)
// Phase B: candidate GEMM with r computed in-kernel (64 working CTAs)
// Phase C: z/candidate finalize + blend (all 128 CTAs, 1 elem/thread)
// tokidx == nullptr -> feedback mode (g_tok).   Cross-CTA data via __ldcg (L1 bypass).
__global__ void __launch_bounds__(256) k_gru(
        const float* __restrict__ emb,
        const int*   __restrict__ tokidx, int tokstride,
        const float* __restrict__ Wx,
        const float* __restrict__ Wh,
        const float* __restrict__ bias,
        int src, int nsteps, unsigned bar_base)
{
    __shared__ __align__(16) float As[64][68];
    __shared__ __align__(16) float Ws[64][68];

    int bx = blockIdx.x;
    int t  = threadIdx.x;
    unsigned nbar = bar_base;

    for (int s = 0; s < nsteps; s++) {
        // ================= Phase A: gate partials =================
        if (bx < 112) {
            bool xpart = (bx < 48);
            int jt, kc, koff, slot;
            const float* W;
            if (xpart) { jt = bx >> 1;            kc = bx & 1; koff = kc * 128; W = Wx; slot = 4 + kc; }
            else       { int i = bx - 48; jt = i >> 2; kc = i & 3; koff = kc * 128; W = Wh; slot = kc; }
            int j0   = jt * 64;
            int jj4  = (t & 15) * 4;
            int brow = t >> 4;

            float acc[4][4];
            #pragma unroll
            for (int i = 0; i < 4; i++) { acc[i][0]=0.f; acc[i][1]=0.f; acc[i][2]=0.f; acc[i][3]=0.f; }

            for (int sc = 0; sc < 2; sc++) {
                int k0 = koff + sc * 64;
                for (int l = t; l < 4096; l += 256) {
                    int b = l >> 6, kk = l & 63;
                    float v;
                    if (xpart) {
                        int row = (tokidx != nullptr) ? tokidx[b * tokstride + s] : g_tok[b];
                        v = emb[(size_t)row * EE + k0 + kk];
                    } else {
                        v = __ldcg(&g_h[src][b * HH + k0 + kk]);
                    }
                    As[b][kk] = v;
                }
                for (int l = t; l < 4096; l += 256) {
                    int kk = l >> 6, jj = l & 63;
                    Ws[kk][jj] = W[(size_t)(k0 + kk) * H3 + j0 + jj];
                }
                __syncthreads();
                #pragma unroll 8
                for (int kk = 0; kk < 64; kk++) {
                    float4 w = *(const float4*)&Ws[kk][jj4];
                    #pragma unroll
                    for (int i = 0; i < 4; i++) {
                        float a = As[brow + 16 * i][kk];
                        acc[i][0] += a * w.x; acc[i][1] += a * w.y;
                        acc[i][2] += a * w.z; acc[i][3] += a * w.w;
                    }
                }
                __syncthreads();
            }
            float* dst = g_gpart[slot];
            #pragma unroll
            for (int i = 0; i < 4; i++) {
                int b = brow + 16 * i;
                *(float4*)&dst[b * H3 + j0 + jj4] =
                    make_float4(acc[i][0], acc[i][1], acc[i][2], acc[i][3]);
            }
        }
        nbar++; grid_bar(nbar * GRU_CTAS);

        // ================= Phase B: candidate GEMM =================
        if (bx < 64) {
            int jt = bx >> 3, kc = bx & 7;
            int j0 = jt * 64, k0 = kc * 64;
            int jj4 = (t & 15) * 4, brow = t >> 4;

            for (int l = t; l < 4096; l += 256) {
                int b = l >> 6, kk = l & 63;
                int j = 512 + k0 + kk;             // r-gate column
                int idx = b * H3 + j;
                float ssum = bias[j]
                    + __ldcg(&g_gpart[0][idx]) + __ldcg(&g_gpart[1][idx])
                    + __ldcg(&g_gpart[2][idx]) + __ldcg(&g_gpart[3][idx])
                    + __ldcg(&g_gpart[4][idx]) + __ldcg(&g_gpart[5][idx]);
                As[b][kk] = sigf(ssum) * __ldcg(&g_h[src][b * HH + k0 + kk]);
            }
            for (int l = t; l < 4096; l += 256) {
                int kk = l >> 6, jj = l & 63;
                Ws[kk][jj] = Wh[(size_t)(k0 + kk) * H3 + 1024 + j0 + jj];
            }
            __syncthreads();
            float acc[4][4];
            #pragma unroll
            for (int i = 0; i < 4; i++) { acc[i][0]=0.f; acc[i][1]=0.f; acc[i][2]=0.f; acc[i][3]=0.f; }
            #pragma unroll 8
            for (int kk = 0; kk < 64; kk++) {
                float4 w = *(const float4*)&Ws[kk][jj4];
                #pragma unroll
                for (int i = 0; i < 4; i++) {
                    float a = As[brow + 16 * i][kk];
                    acc[i][0] += a * w.x; acc[i][1] += a * w.y;
                    acc[i][2] += a * w.z; acc[i][3] += a * w.w;
                }
            }
            float* dst = g_hpart[kc];
            #pragma unroll
            for (int i = 0; i < 4; i++) {
                int b = brow + 16 * i;
                *(float4*)&dst[b * HH + j0 + jj4] =
                    make_float4(acc[i][0], acc[i][1], acc[i][2], acc[i][3]);
            }
            __syncthreads();
        }
        nbar++; grid_bar(nbar * GRU_CTAS);

        // ================= Phase C: finalize =================
        {
            int idx = bx * 256 + t;                // 128*256 = 32768 = BB*HH
            int b = idx >> 9, j = idx & 511;
            int gz = b * H3 + j;
            float zs = bias[j]
                + __ldcg(&g_gpart[0][gz]) + __ldcg(&g_gpart[1][gz])
                + __ldcg(&g_gpart[2][gz]) + __ldcg(&g_gpart[3][gz])
                + __ldcg(&g_gpart[4][gz]) + __ldcg(&g_gpart[5][gz]);
            float z = sigf(zs);
            int gh = b * H3 + 1024 + j;
            float sc = bias[1024 + j] + __ldcg(&g_gpart[4][gh]) + __ldcg(&g_gpart[5][gh]);
            #pragma unroll
            for (int sl = 0; sl < 8; sl++) sc += __ldcg(&g_hpart[sl][idx]);
            float hh = tanhf(sc);
            float hp = __ldcg(&g_h[src][idx]);
            float hn = z * hp + (1.0f - z) * hh;
            g_h[1 - src][idx] = hn;
            g_hb[idx] = __float2bfloat16(hn);
        }
        nbar++; grid_bar(nbar * GRU_CTAS);

        src ^= 1;
    }
}

// -------------------- tensor-core fc: logits = h @ fc_W + b --------------------
__device__ __forceinline__ void mma16816(float* d, const uint32_t* a, const uint32_t* b) {
    asm volatile(
        "mma.sync.aligned.m16n8k16.row.col.f32.bf16.bf16.f32 "
        "{%0,%1,%2,%3},{%4,%5,%6,%7},{%8,%9},{%0,%1,%2,%3};\n"
        : "+f"(d[0]), "+f"(d[1]), "+f"(d[2]), "+f"(d[3])
        : "r"(a[0]), "r"(a[1]), "r"(a[2]), "r"(a[3]), "r"(b[0]), "r"(b[1]));
}
__device__ __forceinline__ void ldsm4(uint32_t* a, const void* p) {
    uint32_t saddr = (uint32_t)__cvta_generic_to_shared(p);
    asm volatile("ldmatrix.sync.aligned.m8n8.x4.shared.b16 {%0,%1,%2,%3},[%4];\n"
        : "=r"(a[0]), "=r"(a[1]), "=r"(a[2]), "=r"(a[3]) : "r"(saddr));
}

// grid = 125 CTAs x 256 threads (8 warps). CTA: M=64 (all), N=256 (32 per warp).
// A (h, bf16) staged in smem per k-half; B fragments loaded straight from g_wt (L2-hot).
#define HS_STRIDE 264   // 256 + 8 pad: 4-bank row shift -> conflict-free ldmatrix
__global__ void __launch_bounds__(256) k_fc(const float* __restrict__ fcb) {
    __shared__ __align__(16) __nv_bfloat16 Hs[64][HS_STRIDE];
    int t = threadIdx.x;
    int warp = t >> 5, lane = t & 31;
    int g = lane >> 2, tig = lane & 3;
    int vbase = blockIdx.x * 256 + warp * 32;

    float acc[4][4][4];
    #pragma unroll
    for (int m = 0; m < 4; m++)
        #pragma unroll
        for (int n = 0; n < 4; n++)
            { acc[m][n][0]=0.f; acc[m][n][1]=0.f; acc[m][n][2]=0.f; acc[m][n][3]=0.f; }

    // ldmatrix source coords for this lane
    int lr  = lane & 7;
    int sel = lane >> 3;
    int arow_off = lr + (sel & 1) * 8;
    int acol_off = (sel >> 1) * 8;

    for (int kh = 0; kh < 2; kh++) {
        int k0g = kh * 256;
        __syncthreads();   // protect Hs reads of previous half
        for (int l = t; l < 2048; l += 256) {          // 64 rows x 32 uint4
            int row = l >> 5, ch = l & 31;
            const uint4* srcp = (const uint4*)(g_hb + row * HH + k0g);
            *(uint4*)&Hs[row][ch * 8] = srcp[ch];
        }
        __syncthreads();

        // B prefetch for ks=0
        uint32_t bcur[4][2], bnxt[4][2];
        #pragma unroll
        for (int nt = 0; nt < 4; nt++) {
            const __nv_bfloat16* wr = g_wt + (size_t)(vbase + nt * 8 + g) * HH + k0g;
            bcur[nt][0] = *(const uint32_t*)(wr + 2 * tig);
            bcur[nt][1] = *(const uint32_t*)(wr + 8 + 2 * tig);
        }

        for (int ks = 0; ks < 16; ks++) {
            int kl = ks * 16;
            if (ks < 15) {
                int kn = kl + 16;
                #pragma unroll
                for (int nt = 0; nt < 4; nt++) {
                    const __nv_bfloat16* wr = g_wt + (size_t)(vbase + nt * 8 + g) * HH + k0g + kn;
                    bnxt[nt][0] = *(const uint32_t*)(wr + 2 * tig);
                    bnxt[nt][1] = *(const uint32_t*)(wr + 8 + 2 * tig);
                }
            }
            uint32_t afr[4][4];
            #pragma unroll
            for (int mt = 0; mt < 4; mt++)
                ldsm4(afr[mt], &Hs[mt * 16 + arow_off][kl + acol_off]);
            #pragma unroll
            for (int mt = 0; mt < 4; mt++)
                #pragma unroll
                for (int nt = 0; nt < 4; nt++)
                    mma16816(acc[mt][nt], afr[mt], bcur[nt]);
            if (ks < 15) {
                #pragma unroll
                for (int nt = 0; nt < 4; nt++) { bcur[nt][0] = bnxt[nt][0]; bcur[nt][1] = bnxt[nt][1]; }
            }
        }
    }

    // epilogue: add bias, store f32 logits
    #pragma unroll
    for (int nt = 0; nt < 4; nt++) {
        int col = vbase + nt * 8 + 2 * tig;
        float2 bv = *(const float2*)(fcb + col);
        #pragma unroll
        for (int mt = 0; mt < 4; mt++) {
            int r0 = mt * 16 + g;
            float2 o0 = make_float2(acc[mt][nt][0] + bv.x, acc[mt][nt][1] + bv.y);
            float2 o1 = make_float2(acc[mt][nt][2] + bv.x, acc[mt][nt][3] + bv.y);
            *(float2*)&g_logits[(size_t)r0 * VV + col]       = o0;
            *(float2*)&g_logits[(size_t)(r0 + 8) * VV + col] = o1;
        }
    }
}

// -------------------- per-batch loss + argmax --------------------
// ce = log(sum_v exp(p_v)) - p_target, p = softmax(logits). Logits tiny -> no shift.
__global__ void k_loss(const int* __restrict__ targ, int tcol) {
    __shared__ float sred[256];
    __shared__ float mred[256];
    __shared__ int   ired[256];
    int b = blockIdx.x, t = threadIdx.x;
    const float* lg = g_logits + (size_t)b * VV;

    float m = -3.4e38f; int mi = 0; float s1 = 0.f;
    for (int v = t; v < VV; v += 256) {
        float l = lg[v];
        s1 += expf(l);
        if (l > m) { m = l; mi = v; }
    }
    mred[t] = m; ired[t] = mi; sred[t] = s1;
    __syncthreads();
    for (int off = 128; off; off >>= 1) {
        if (t < off) {
            float mo = mred[t + off]; int io = ired[t + off];
            if (mo > mred[t] || (mo == mred[t] && io < ired[t])) { mred[t] = mo; ired[t] = io; }
            sred[t] += sred[t + off];
        }
        __syncthreads();
    }
    float inv_s1 = 1.0f / sred[0];
    int argmax = ired[0];
    __syncthreads();

    float s2 = 0.f;
    for (int v = t; v < VV; v += 256)
        s2 += expf(expf(lg[v]) * inv_s1);
    sred[t] = s2;
    __syncthreads();
    for (int off = 128; off; off >>= 1) {
        if (t < off) sred[t] += sred[t + off];
        __syncthreads();
    }
    if (t == 0) {
        int tgt = targ[b * TT + tcol];
        float pt = expf(lg[tgt]) * inv_s1;
        g_ce[b] = logf(sred[0]) - pt;
        g_tok[b] = argmax;
    }
}

// -------------------- deterministic masked-mean accumulate --------------------
__global__ void k_losssum(const int* __restrict__ targ, int tcol, float* out) {
    int t = threadIdx.x;  // 32
    float a = g_ce[t]      * ((targ[t * TT + tcol]        != 0) ? 1.f : 0.f);
    float c = g_ce[t + 32] * ((targ[(t + 32) * TT + tcol] != 0) ? 1.f : 0.f);
    float v = a + c;
    #pragma unroll
    for (int off = 16; off; off >>= 1)
        v += __shfl_down_sync(0xffffffffu, v, off);
    if (t == 0) out[0] += v * (1.0f / 64.0f);
}

// -------------------- launch --------------------
extern "C" void kernel_launch(void* const* d_in, const int* in_sizes, int n_in,
                              void* d_out, int out_size)
{
    const int*   inp     = (const int*)  d_in[0];
    const int*   targ    = (const int*)  d_in[1];
    const float* emb_enc = (const float*)d_in[2];
    const float* enc_Wx  = (const float*)d_in[3];
    const float* enc_Wh  = (const float*)d_in[4];
    const float* enc_b   = (const float*)d_in[5];
    const float* emb_dec = (const float*)d_in[6];
    const float* dec_Wx  = (const float*)d_in[7];
    const float* dec_Wh  = (const float*)d_in[8];
    const float* dec_b   = (const float*)d_in[9];
    const float* fc_W    = (const float*)d_in[10];
    const float* fc_b    = (const float*)d_in[11];
    float* out = (float*)d_out;

    k_init<<<BB, HH>>>(out);
    k_prept<<<dim3(1000, 16), 256>>>(fc_W);

    unsigned barb = 0;
    // encoder: 64 GRU steps in ONE launch
    k_gru<<<GRU_CTAS, 256>>>(emb_enc, inp, SS, enc_Wx, enc_Wh, enc_b, 0, SS, barb);
    barb += 3 * SS;

    int src = 0;   // SS even -> final encoder state in g_h[0]
    for (int tt = 1; tt < TT; tt++) {
        k_gru<<<GRU_CTAS, 256>>>(emb_dec, nullptr, 0, dec_Wx, dec_Wh, dec_b, src, 1, barb);
        barb += 3;
        src ^= 1;
        k_fc<<<125, 256>>>(fc_b);
        k_loss<<<BB, 256>>>(targ, tt);
        k_losssum<<<1, 32>>>(targ, tt, out);
    }
}

// round 9
// speedup vs baseline: 1.4151x; 1.4151x over previous
#include <cuda_runtime.h>
#include <cuda_bf16.h>
#include <math.h>
#include <stdint.h>

// Problem constants
#define BB   64      // batch
#define SS   64      // encoder seq len
#define TT   32      // decoder target len
#define VV   32000   // vocab
#define EE   256     // embedding
#define HH   512     // hidden
#define H3   1536    // 3*H

#define GCTAS 112    // persistent GRU grid (single wave)

// -------------------- device scratch (static, no allocation) --------------------
__device__ __align__(16) float          g_h[2][BB * HH];     // hidden, double buffered
__device__ __align__(16) float          g_gpart[6][BB * H3]; // split-K partials, gates
__device__ __align__(16) float          g_hpart[8][BB * HH]; // split-K partials, candidate
__device__ __align__(16) __nv_bfloat16  g_hb[BB * HH];       // hidden bf16 (fc A operand)
__device__ __align__(16) __nv_bfloat16  g_wt[(size_t)VV * HH]; // fc_W^T [v][k] bf16
__device__ __align__(16) float          g_logits[(size_t)BB * VV];
__device__ float                        g_ce[BB];
__device__ int                          g_tok[BB];
__device__ unsigned                     g_bar;               // grid barrier counter

__device__ __forceinline__ float sigf(float x) { return 1.0f / (1.0f + expf(-x)); }

// Software grid barrier: hot spin on one L2 line (fast wake, no nanosleep quantization).
__device__ __forceinline__ void gbar(unsigned target) {
    __syncthreads();
    if (threadIdx.x == 0) {
        __threadfence();                       // release: publish phase stores
        atomicAdd(&g_bar, 1u);
        volatile unsigned* vp = &g_bar;
        while (*vp < target) {}
    }
    __syncthreads();
    __threadfence();                           // acquire side
}

// -------------------- init --------------------
__global__ void k_init(float* out) {
    int b = blockIdx.x, t = threadIdx.x;
    g_h[0][b * HH + t] = 0.0f;
    if (t == 0) g_tok[b] = 1;                  // BEGIN token
    if (b == 0 && t == 0) { out[0] = 0.0f; g_bar = 0u; }
}

// -------------------- fc_W [k][v] fp32 -> g_wt [v][k] bf16 (transpose) --------------------
// grid = (1000, 16), 256 threads; 32x32 tiles.   (proven in round 4)
__global__ void k_prept(const float* __restrict__ fcW) {
    __shared__ float Ts[32][33];
    int v0 = blockIdx.x * 32, k0 = blockIdx.y * 32;
    int c = threadIdx.x & 31, r8 = threadIdx.x >> 5;
    #pragma unroll
    for (int i = 0; i < 4; i++) {
        int r = r8 + 8 * i;
        Ts[r][c] = fcW[(size_t)(k0 + r) * VV + v0 + c];
    }
    __syncthreads();
    #pragma unroll
    for (int i = 0; i < 4; i++) {
        int r = r8 + 8 * i;
        g_wt[(size_t)(v0 + r) * HH + k0 + c] = __float2bfloat16(Ts[c][r]);
    }
}

// -------------------- fused GRU sequence kernel (112 CTAs, FFMA, proven structure) -------
// Phase A: gate GEMM split-K partials (112 CTAs: 48 x-part + 64 h-part)
// Phase B: candidate GEMM with r computed in-kernel (64 CTAs)
// Phase C: z/candidate finalize + blend (all CTAs, strided loop)
// tokidx == nullptr -> feedback mode (g_tok). Cross-CTA data via __ldcg.
__global__ void __launch_bounds__(256) k_gru(
        const float* __restrict__ emb,
        const int*   __restrict__ tokidx, int tokstride,
        const float* __restrict__ Wx,
        const float* __restrict__ Wh,
        const float* __restrict__ bias,
        int src, int nsteps, unsigned bar_base)
{
    __shared__ __align__(16) float As[64][68];
    __shared__ __align__(16) float Ws[64][68];

    int bx = blockIdx.x;
    int t  = threadIdx.x;
    unsigned nbar = bar_base;

    for (int s = 0; s < nsteps; s++) {
        // ================= Phase A: gate partials =================
        {
            bool xpart = (bx < 48);
            int jt, kc, koff, slot;
            const float* W;
            if (xpart) { jt = bx >> 1;            kc = bx & 1; koff = kc * 128; W = Wx; slot = 4 + kc; }
            else       { int i = bx - 48; jt = i >> 2; kc = i & 3; koff = kc * 128; W = Wh; slot = kc; }
            int j0   = jt * 64;
            int jj4  = (t & 15) * 4;
            int brow = t >> 4;

            float acc[4][4];
            #pragma unroll
            for (int i = 0; i < 4; i++) { acc[i][0]=0.f; acc[i][1]=0.f; acc[i][2]=0.f; acc[i][3]=0.f; }

            for (int sc = 0; sc < 2; sc++) {
                int k0 = koff + sc * 64;
                // activation tile: 64 rows x 16 float4
                for (int l = t; l < 1024; l += 256) {
                    int b = l >> 4, c4 = (l & 15) * 4;
                    float4 v;
                    if (xpart) {
                        int row = (tokidx != nullptr) ? tokidx[b * tokstride + s] : g_tok[b];
                        v = *(const float4*)(emb + (size_t)row * EE + k0 + c4);
                    } else {
                        v = __ldcg((const float4*)&g_h[src][b * HH + k0 + c4]);
                    }
                    *(float4*)&As[b][c4] = v;
                }
                // weight tile: 64 k-rows x 16 float4
                for (int l = t; l < 1024; l += 256) {
                    int kk = l >> 4, j4 = (l & 15) * 4;
                    *(float4*)&Ws[kk][j4] = *(const float4*)(W + (size_t)(k0 + kk) * H3 + j0 + j4);
                }
                __syncthreads();
                #pragma unroll 8
                for (int kk = 0; kk < 64; kk++) {
                    float4 w = *(const float4*)&Ws[kk][jj4];
                    #pragma unroll
                    for (int i = 0; i < 4; i++) {
                        float a = As[brow + 16 * i][kk];
                        acc[i][0] += a * w.x; acc[i][1] += a * w.y;
                        acc[i][2] += a * w.z; acc[i][3] += a * w.w;
                    }
                }
                __syncthreads();
            }
            float* dst = g_gpart[slot];
            #pragma unroll
            for (int i = 0; i < 4; i++) {
                int b = brow + 16 * i;
                *(float4*)&dst[b * H3 + j0 + jj4] =
                    make_float4(acc[i][0], acc[i][1], acc[i][2], acc[i][3]);
            }
        }
        nbar++; gbar(nbar * GCTAS);

        // ================= Phase B: candidate GEMM =================
        if (bx < 64) {
            int jt = bx >> 3, kc = bx & 7;
            int j0 = jt * 64, k0 = kc * 64;
            int jj4 = (t & 15) * 4, brow = t >> 4;

            // staging: r = sigmoid(sum of 6 partial slots + bias); As = r * h   (float4)
            for (int l = t; l < 1024; l += 256) {
                int b = l >> 4, k4 = (l & 15) * 4;
                int j = 512 + k0 + k4;                 // r-gate columns
                int idx = b * H3 + j;
                float4 s0 = __ldcg((const float4*)&g_gpart[0][idx]);
                float4 s1 = __ldcg((const float4*)&g_gpart[1][idx]);
                float4 s2 = __ldcg((const float4*)&g_gpart[2][idx]);
                float4 s3 = __ldcg((const float4*)&g_gpart[3][idx]);
                float4 s4 = __ldcg((const float4*)&g_gpart[4][idx]);
                float4 s5 = __ldcg((const float4*)&g_gpart[5][idx]);
                float4 bv = *(const float4*)&bias[j];
                float4 hv = __ldcg((const float4*)&g_h[src][b * HH + k0 + k4]);
                float4 r;
                r.x = sigf(bv.x + s0.x + s1.x + s2.x + s3.x + s4.x + s5.x) * hv.x;
                r.y = sigf(bv.y + s0.y + s1.y + s2.y + s3.y + s4.y + s5.y) * hv.y;
                r.z = sigf(bv.z + s0.z + s1.z + s2.z + s3.z + s4.z + s5.z) * hv.z;
                r.w = sigf(bv.w + s0.w + s1.w + s2.w + s3.w + s4.w + s5.w) * hv.w;
                *(float4*)&As[b][k4] = r;
            }
            for (int l = t; l < 1024; l += 256) {
                int kk = l >> 4, j4 = (l & 15) * 4;
                *(float4*)&Ws[kk][j4] =
                    *(const float4*)(Wh + (size_t)(k0 + kk) * H3 + 1024 + j0 + j4);
            }
            __syncthreads();
            float acc[4][4];
            #pragma unroll
            for (int i = 0; i < 4; i++) { acc[i][0]=0.f; acc[i][1]=0.f; acc[i][2]=0.f; acc[i][3]=0.f; }
            #pragma unroll 8
            for (int kk = 0; kk < 64; kk++) {
                float4 w = *(const float4*)&Ws[kk][jj4];
                #pragma unroll
                for (int i = 0; i < 4; i++) {
                    float a = As[brow + 16 * i][kk];
                    acc[i][0] += a * w.x; acc[i][1] += a * w.y;
                    acc[i][2] += a * w.z; acc[i][3] += a * w.w;
                }
            }
            float* dst = g_hpart[kc];
            #pragma unroll
            for (int i = 0; i < 4; i++) {
                int b = brow + 16 * i;
                *(float4*)&dst[b * HH + j0 + jj4] =
                    make_float4(acc[i][0], acc[i][1], acc[i][2], acc[i][3]);
            }
            __syncthreads();
        }
        nbar++; gbar(nbar * GCTAS);

        // ================= Phase C: finalize (strided over 112 CTAs) =================
        for (int idx = bx * 256 + t; idx < BB * HH; idx += GCTAS * 256) {
            int b = idx >> 9, j = idx & 511;
            int gz = b * H3 + j;                      // z-gate column
            float zs = bias[j]
                + __ldcg(&g_gpart[0][gz]) + __ldcg(&g_gpart[1][gz])
                + __ldcg(&g_gpart[2][gz]) + __ldcg(&g_gpart[3][gz])
                + __ldcg(&g_gpart[4][gz]) + __ldcg(&g_gpart[5][gz]);
            float z = sigf(zs);
            int gh = b * H3 + 1024 + j;               // candidate x-part column
            float sc2 = bias[1024 + j] + __ldcg(&g_gpart[4][gh]) + __ldcg(&g_gpart[5][gh]);
            #pragma unroll
            for (int sl = 0; sl < 8; sl++) sc2 += __ldcg(&g_hpart[sl][idx]);
            float hh = tanhf(sc2);
            float hp = __ldcg(&g_h[src][idx]);
            float hn = z * hp + (1.0f - z) * hh;
            g_h[1 - src][idx] = hn;
            g_hb[idx] = __float2bfloat16(hn);
        }
        nbar++; gbar(nbar * GCTAS);

        src ^= 1;
    }
}

// -------------------- tensor-core fc: logits = h @ fc_W + b  (proven in round 4) --------
__device__ __forceinline__ void mma16816(float* d, const uint32_t* a, const uint32_t* b) {
    asm volatile(
        "mma.sync.aligned.m16n8k16.row.col.f32.bf16.bf16.f32 "
        "{%0,%1,%2,%3},{%4,%5,%6,%7},{%8,%9},{%0,%1,%2,%3};\n"
        : "+f"(d[0]), "+f"(d[1]), "+f"(d[2]), "+f"(d[3])
        : "r"(a[0]), "r"(a[1]), "r"(a[2]), "r"(a[3]), "r"(b[0]), "r"(b[1]));
}
__device__ __forceinline__ void ldsm4(uint32_t* a, const void* p) {
    uint32_t saddr = (uint32_t)__cvta_generic_to_shared(p);
    asm volatile("ldmatrix.sync.aligned.m8n8.x4.shared.b16 {%0,%1,%2,%3},[%4];\n"
        : "=r"(a[0]), "=r"(a[1]), "=r"(a[2]), "=r"(a[3]) : "r"(saddr));
}

#define HS_STRIDE 264   // 256 + 8 pad: conflict-free ldmatrix
__global__ void __launch_bounds__(256) k_fc(const float* __restrict__ fcb) {
    __shared__ __align__(16) __nv_bfloat16 Hs[64][HS_STRIDE];
    int t = threadIdx.x;
    int warp = t >> 5, lane = t & 31;
    int g = lane >> 2, tig = lane & 3;
    int vbase = blockIdx.x * 256 + warp * 32;

    float acc[4][4][4];
    #pragma unroll
    for (int m = 0; m < 4; m++)
        #pragma unroll
        for (int n = 0; n < 4; n++)
            { acc[m][n][0]=0.f; acc[m][n][1]=0.f; acc[m][n][2]=0.f; acc[m][n][3]=0.f; }

    int lr  = lane & 7;
    int sel = lane >> 3;
    int arow_off = lr + (sel & 1) * 8;
    int acol_off = (sel >> 1) * 8;

    for (int kh = 0; kh < 2; kh++) {
        int k0g = kh * 256;
        __syncthreads();
        for (int l = t; l < 2048; l += 256) {
            int row = l >> 5, ch = l & 31;
            const uint4* srcp = (const uint4*)(g_hb + row * HH + k0g);
            *(uint4*)&Hs[row][ch * 8] = srcp[ch];
        }
        __syncthreads();

        uint32_t bcur[4][2], bnxt[4][2];
        #pragma unroll
        for (int nt = 0; nt < 4; nt++) {
            const __nv_bfloat16* wr = g_wt + (size_t)(vbase + nt * 8 + g) * HH + k0g;
            bcur[nt][0] = *(const uint32_t*)(wr + 2 * tig);
            bcur[nt][1] = *(const uint32_t*)(wr + 8 + 2 * tig);
        }

        for (int ks = 0; ks < 16; ks++) {
            int kl = ks * 16;
            if (ks < 15) {
                int kn = kl + 16;
                #pragma unroll
                for (int nt = 0; nt < 4; nt++) {
                    const __nv_bfloat16* wr = g_wt + (size_t)(vbase + nt * 8 + g) * HH + k0g + kn;
                    bnxt[nt][0] = *(const uint32_t*)(wr + 2 * tig);
                    bnxt[nt][1] = *(const uint32_t*)(wr + 8 + 2 * tig);
                }
            }
            uint32_t afr[4][4];
            #pragma unroll
            for (int mt = 0; mt < 4; mt++)
                ldsm4(afr[mt], &Hs[mt * 16 + arow_off][kl + acol_off]);
            #pragma unroll
            for (int mt = 0; mt < 4; mt++)
                #pragma unroll
                for (int nt = 0; nt < 4; nt++)
                    mma16816(acc[mt][nt], afr[mt], bcur[nt]);
            if (ks < 15) {
                #pragma unroll
                for (int nt = 0; nt < 4; nt++) { bcur[nt][0] = bnxt[nt][0]; bcur[nt][1] = bnxt[nt][1]; }
            }
        }
    }

    #pragma unroll
    for (int nt = 0; nt < 4; nt++) {
        int col = vbase + nt * 8 + 2 * tig;
        float2 bv = *(const float2*)(fcb + col);
        #pragma unroll
        for (int mt = 0; mt < 4; mt++) {
            int r0 = mt * 16 + g;
            float2 o0 = make_float2(acc[mt][nt][0] + bv.x, acc[mt][nt][1] + bv.y);
            float2 o1 = make_float2(acc[mt][nt][2] + bv.x, acc[mt][nt][3] + bv.y);
            *(float2*)&g_logits[(size_t)r0 * VV + col]       = o0;
            *(float2*)&g_logits[(size_t)(r0 + 8) * VV + col] = o1;
        }
    }
}

// -------------------- per-batch loss + argmax --------------------
__global__ void k_loss(const int* __restrict__ targ, int tcol) {
    __shared__ float sred[256];
    __shared__ float mred[256];
    __shared__ int   ired[256];
    int b = blockIdx.x, t = threadIdx.x;
    const float* lg = g_logits + (size_t)b * VV;

    float m = -3.4e38f; int mi = 0; float s1 = 0.f;
    for (int v = t; v < VV; v += 256) {
        float l = lg[v];
        s1 += expf(l);
        if (l > m) { m = l; mi = v; }
    }
    mred[t] = m; ired[t] = mi; sred[t] = s1;
    __syncthreads();
    for (int off = 128; off; off >>= 1) {
        if (t < off) {
            float mo = mred[t + off]; int io = ired[t + off];
            if (mo > mred[t] || (mo == mred[t] && io < ired[t])) { mred[t] = mo; ired[t] = io; }
            sred[t] += sred[t + off];
        }
        __syncthreads();
    }
    float inv_s1 = 1.0f / sred[0];
    int argmax = ired[0];
    __syncthreads();

    float s2 = 0.f;
    for (int v = t; v < VV; v += 256)
        s2 += expf(expf(lg[v]) * inv_s1);
    sred[t] = s2;
    __syncthreads();
    for (int off = 128; off; off >>= 1) {
        if (t < off) sred[t] += sred[t + off];
        __syncthreads();
    }
    if (t == 0) {
        int tgt = targ[b * TT + tcol];
        float pt = expf(lg[tgt]) * inv_s1;
        g_ce[b] = logf(sred[0]) - pt;
        g_tok[b] = argmax;
    }
}

// -------------------- deterministic masked-mean accumulate --------------------
__global__ void k_losssum(const int* __restrict__ targ, int tcol, float* out) {
    int t = threadIdx.x;  // 32
    float a = g_ce[t]      * ((targ[t * TT + tcol]        != 0) ? 1.f : 0.f);
    float c = g_ce[t + 32] * ((targ[(t + 32) * TT + tcol] != 0) ? 1.f : 0.f);
    float v = a + c;
    #pragma unroll
    for (int off = 16; off; off >>= 1)
        v += __shfl_down_sync(0xffffffffu, v, off);
    if (t == 0) out[0] += v * (1.0f / 64.0f);
}

// -------------------- launch --------------------
extern "C" void kernel_launch(void* const* d_in, const int* in_sizes, int n_in,
                              void* d_out, int out_size)
{
    const int*   inp     = (const int*)  d_in[0];
    const int*   targ    = (const int*)  d_in[1];
    const float* emb_enc = (const float*)d_in[2];
    const float* enc_Wx  = (const float*)d_in[3];
    const float* enc_Wh  = (const float*)d_in[4];
    const float* enc_b   = (const float*)d_in[5];
    const float* emb_dec = (const float*)d_in[6];
    const float* dec_Wx  = (const float*)d_in[7];
    const float* dec_Wh  = (const float*)d_in[8];
    const float* dec_b   = (const float*)d_in[9];
    const float* fc_W    = (const float*)d_in[10];
    const float* fc_b    = (const float*)d_in[11];
    float* out = (float*)d_out;

    k_init<<<BB, HH>>>(out);
    k_prept<<<dim3(1000, 16), 256>>>(fc_W);

    unsigned barb = 0;
    // encoder: 64 GRU steps in ONE launch
    k_gru<<<GCTAS, 256>>>(emb_enc, inp, SS, enc_Wx, enc_Wh, enc_b, 0, SS, barb);
    barb += 3 * SS;

    int src = 0;   // SS even -> final encoder state in g_h[0]
    for (int tt = 1; tt < TT; tt++) {
        k_gru<<<GCTAS, 256>>>(emb_dec, nullptr, 0, dec_Wx, dec_Wh, dec_b, src, 1, barb);
        barb += 3;
        src ^= 1;
        k_fc<<<125, 256>>>(fc_b);
        k_loss<<<BB, 256>>>(targ, tt);
        k_losssum<<<1, 32>>>(targ, tt, out);
    }
}